// round 6
// baseline (speedup 1.0000x reference)
#include <cuda_runtime.h>
#include <cuda_bf16.h>
#include <math.h>
#include <stdint.h>

#define NN 50000
#define EE 800000
#define FIN 512
#define F1 128      // H1*C1
#define H1 8
#define C1 16
#define F2 40       // H2*C2 = num classes
#define NEG 0.2f

// ---------------- scratch (device globals; no allocation allowed) ------------
__device__ __nv_bfloat16 g_xb[NN * FIN];      // x in bf16
__device__ __nv_bfloat16 g_w1t[F1 * FIN];     // W1^T bf16 (n-major, k contiguous)
__device__ __nv_bfloat16 g_w2t[64 * F1];      // W2^T bf16 padded to 64 cols
__device__ __nv_bfloat16 g_h1b[NN * F1];      // layer1 features bf16
__device__ __nv_bfloat16 g_x2b[NN * F1];      // elu(agg1+b1) bf16
__device__ float g_asrc1[NN * H1];
__device__ float g_adst1[NN * H1];
__device__ float g_h2[NN * F2];
__device__ float g_asrc2[NN];
__device__ float g_adst2[NN];
__device__ int   g_counts[NN];
__device__ int   g_rowptr[NN + 1];
__device__ int   g_cursor[NN];
__device__ int   g_esrc[EE + NN];
__device__ int   g_is64;

// ---------------- input conversion -------------------------------------------
__global__ void k_convw(const float* __restrict__ W1, const float* __restrict__ W2) {
    int i = blockIdx.x * blockDim.x + threadIdx.x;
    if (i < F1 * FIN) {                          // W1^T
        int n = i >> 9, k = i & 511;
        g_w1t[i] = __float2bfloat16(W1[k * F1 + n]);
    }
    if (i < 64 * F1) {                           // W2^T (pad cols 40..63 with 0)
        int n = i >> 7, k = i & 127;
        g_w2t[i] = __float2bfloat16(n < F2 ? W2[k * F2 + n] : 0.f);
    }
}

__global__ void k_convx(const float* __restrict__ x) {
    int i = blockIdx.x * blockDim.x + threadIdx.x;   // per float4
    if (i >= NN * FIN / 4) return;
    float4 v = ((const float4*)x)[i];
    __nv_bfloat162 p0 = __floats2bfloat162_rn(v.x, v.y);
    __nv_bfloat162 p1 = __floats2bfloat162_rn(v.z, v.w);
    uint2 o;
    o.x = *(uint32_t*)&p0;
    o.y = *(uint32_t*)&p1;
    ((uint2*)g_xb)[i] = o;
}

// ---------------- CSR build --------------------------------------------------
__global__ void k_init(const int* __restrict__ ei32) {
    int i = blockIdx.x * blockDim.x + threadIdx.x;
    if (i < NN) g_counts[i] = 1;   // self-loop
    if (i == 0) {
        int z = 0;
        #pragma unroll 1
        for (int t = 0; t < 64; t++) if (ei32[2 * t + 1] == 0) z++;
        g_is64 = (z == 64) ? 1 : 0;
    }
}

__device__ __forceinline__ int edge_at(const int* ei32, int idx, int is64) {
    return is64 ? ei32[2 * idx] : ei32[idx];
}

__global__ void k_hist(const int* __restrict__ ei32) {
    int i = blockIdx.x * blockDim.x + threadIdx.x;
    if (i >= EE) return;
    int is64 = g_is64;
    int dd = edge_at(ei32, EE + i, is64);
    atomicAdd(&g_counts[dd], 1);
}

#define SCAN_T 1024
#define SCAN_CH ((NN + SCAN_T - 1) / SCAN_T)
__global__ void k_scan() {
    __shared__ int sums[SCAN_T];
    int t = threadIdx.x;
    int b0 = t * SCAN_CH;
    int b1 = min(b0 + SCAN_CH, NN);
    int s = 0;
    for (int i = b0; i < b1; i++) s += g_counts[i];
    sums[t] = s;
    __syncthreads();
    for (int off = 1; off < SCAN_T; off <<= 1) {
        int v = (t >= off) ? sums[t - off] : 0;
        __syncthreads();
        sums[t] += v;
        __syncthreads();
    }
    int offset = (t == 0) ? 0 : sums[t - 1];
    for (int i = b0; i < b1; i++) {
        g_rowptr[i] = offset;
        g_cursor[i] = offset;
        offset += g_counts[i];
    }
    if (t == 0) g_rowptr[NN] = sums[SCAN_T - 1];
}

__global__ void k_scatter(const int* __restrict__ ei32) {
    int i = blockIdx.x * blockDim.x + threadIdx.x;
    if (i >= EE + NN) return;
    int is64 = g_is64;
    int s, dd;
    if (i < EE) { s = edge_at(ei32, i, is64); dd = edge_at(ei32, EE + i, is64); }
    else        { s = dd = i - EE; }
    int pos = atomicAdd(&g_cursor[dd], 1);
    g_esrc[pos] = s;
}

// ---------------- shared GEMM helpers ----------------------------------------
#define SSTR 20             // u32 stride per row (16 used, pad to 20: conflict-free)

__device__ __forceinline__ void cp16(uint32_t dst, const void* src, int bytes) {
    asm volatile("cp.async.cg.shared.global [%0], [%1], 16, %2;"
                 :: "r"(dst), "l"(src), "r"(bytes));
}
__device__ __forceinline__ void cp_commit() {
    asm volatile("cp.async.commit_group;");
}
template <int N> __device__ __forceinline__ void cp_wait() {
    asm volatile("cp.async.wait_group %0;" :: "n"(N));
}

__device__ __forceinline__ void mma_bf16(float c[4], const uint32_t a[4],
                                         const uint32_t b[2]) {
    asm volatile(
        "mma.sync.aligned.m16n8k16.row.col.f32.bf16.bf16.f32 "
        "{%0,%1,%2,%3}, {%4,%5,%6,%7}, {%8,%9}, {%0,%1,%2,%3};"
        : "+f"(c[0]), "+f"(c[1]), "+f"(c[2]), "+f"(c[3])
        : "r"(a[0]), "r"(a[1]), "r"(a[2]), "r"(a[3]), "r"(b[0]), "r"(b[1]));
}

// ---------------- GEMM1: h1 = x @ W1  (50000x512x128, bf16) ------------------
#define G1_BM 128
#define G1_BK 32
#define SBUF (256 * SSTR)   // one stage: 128 A-rows + 128 B-cols

__global__ __launch_bounds__(256, 2) void k_gemm1() {
    __shared__ uint32_t S[2][SBUF];
    int tid = threadIdx.x;
    int lane = tid & 31;
    int warp = tid >> 5;
    int wm = warp >> 1;            // 0..3 : 32 rows each
    int wn = warp & 1;             // 0..1 : 64 cols each
    int g = lane >> 2;             // 0..7
    int t4 = lane & 3;             // 0..3
    int rowBase = blockIdx.x * G1_BM;

    uint32_t sbase = (uint32_t)__cvta_generic_to_shared(&S[0][0]);
    int lr = tid >> 2;             // 0..63
    int lc = tid & 3;              // 0..3 (16B chunk)

    auto stage_load = [&](int buf, int k0) {
        uint32_t b0 = sbase + (uint32_t)buf * (SBUF * 4);
        #pragma unroll
        for (int l = 0; l < 128; l += 64) {
            int row = rowBase + lr + l;
            const void* pa = (row < NN) ? (const void*)&g_xb[(size_t)row * FIN + k0 + lc * 8]
                                        : (const void*)g_xb;
            cp16(b0 + ((lr + l) * SSTR + lc * 4) * 4, pa, (row < NN) ? 16 : 0);
            cp16(b0 + ((128 + lr + l) * SSTR + lc * 4) * 4,
                 &g_w1t[(size_t)(lr + l) * FIN + k0 + lc * 8], 16);
        }
    };

    float acc[2][8][4];
    #pragma unroll
    for (int mt = 0; mt < 2; mt++)
        #pragma unroll
        for (int nt = 0; nt < 8; nt++)
            #pragma unroll
            for (int i = 0; i < 4; i++) acc[mt][nt][i] = 0.f;

    stage_load(0, 0);
    cp_commit();

    #pragma unroll 1
    for (int it = 0; it < FIN / G1_BK; it++) {
        int buf = it & 1;
        if (it + 1 < FIN / G1_BK) {
            stage_load(buf ^ 1, (it + 1) * G1_BK);
            cp_commit();
            cp_wait<1>();
        } else {
            cp_wait<0>();
        }
        __syncthreads();

        const uint32_t* Sb = &S[buf][0];
        #pragma unroll
        for (int ks = 0; ks < 2; ks++) {
            uint32_t a[2][4];
            #pragma unroll
            for (int mt = 0; mt < 2; mt++) {
                int r0 = (wm * 32 + mt * 16 + g) * SSTR + ks * 8 + t4;
                a[mt][0] = Sb[r0];
                a[mt][1] = Sb[r0 + 8 * SSTR];
                a[mt][2] = Sb[r0 + 4];
                a[mt][3] = Sb[r0 + 8 * SSTR + 4];
            }
            #pragma unroll
            for (int nt = 0; nt < 8; nt++) {
                int bi = (128 + wn * 64 + nt * 8 + g) * SSTR + ks * 8 + t4;
                uint32_t b[2] = {Sb[bi], Sb[bi + 4]};
                mma_bf16(acc[0][nt], a[0], b);
                mma_bf16(acc[1][nt], a[1], b);
            }
        }
        __syncthreads();
    }

    // epilogue: write h1 as bf16
    #pragma unroll
    for (int mt = 0; mt < 2; mt++) {
        int row = rowBase + wm * 32 + mt * 16 + g;
        #pragma unroll
        for (int nt = 0; nt < 8; nt++) {
            int col = wn * 64 + nt * 8 + 2 * t4;
            if (row < NN)
                *(__nv_bfloat162*)&g_h1b[(size_t)row * F1 + col] =
                    __floats2bfloat162_rn(acc[mt][nt][0], acc[mt][nt][1]);
            if (row + 8 < NN)
                *(__nv_bfloat162*)&g_h1b[(size_t)(row + 8) * F1 + col] =
                    __floats2bfloat162_rn(acc[mt][nt][2], acc[mt][nt][3]);
        }
    }
}

// ---------------- layer-1 attention coefficients -----------------------------
__global__ void k_attc1(const float* __restrict__ att_src1,
                        const float* __restrict__ att_dst1) {
    int idx = blockIdx.x * blockDim.x + threadIdx.x;   // n*8 + h
    if (idx >= NN * H1) return;
    int h = idx & 7;
    const __nv_bfloat16* hp = &g_h1b[(size_t)(idx >> 3) * F1 + h * C1];
    float s = 0.f, t = 0.f;
    #pragma unroll
    for (int c = 0; c < C1; c++) {
        float v = __bfloat162float(hp[c]);
        s = fmaf(v, att_src1[h * C1 + c], s);
        t = fmaf(v, att_dst1[h * C1 + c], t);
    }
    g_asrc1[idx] = s;
    g_adst1[idx] = t;
}

__device__ __forceinline__ float leaky(float e) { return e > 0.f ? e : NEG * e; }

// ---------------- layer-1 aggregate (128 threads per node) -------------------
__global__ __launch_bounds__(256) void k_agg1(const float* __restrict__ b1) {
    __shared__ float s_part[2][4][8];
    __shared__ float s_inv[2][8];
    __shared__ float s_alpha[2][16 * 8];
    __shared__ int   s_src[2][16];
    int tid = threadIdx.x;
    int grp = tid >> 7;              // 0..1 (node within block)
    int t = tid & 127;
    int n = blockIdx.x * 2 + grp;
    int lane = tid & 31;
    int wig = t >> 5;                // warp in group
    int start = g_rowptr[n], end = g_rowptr[n + 1];

    int h = t & 7;                   // head for alpha work
    int q = t >> 3;                  // edge slot 0..15
    float adst = g_adst1[n * 8 + h];

    // pass 1: per-head exp-sum (denominator)
    float part = 0.f;
    for (int j = start + q; j < end; j += 16) {
        int s = g_esrc[j];
        part += __expf(leaky(g_asrc1[s * 8 + h] + adst));
    }
    part += __shfl_xor_sync(0xffffffffu, part, 8);
    part += __shfl_xor_sync(0xffffffffu, part, 16);
    if (lane < 8) s_part[grp][wig][lane] = part;
    __syncthreads();
    if (t < 8) {
        float d = s_part[grp][0][t] + s_part[grp][1][t] +
                  s_part[grp][2][t] + s_part[grp][3][t];
        s_inv[grp][t] = 1.f / (d + 1e-16f);
    }
    __syncthreads();
    float inv_h = s_inv[grp][h];

    // pass 2: chunked alpha precompute + channel-parallel gather
    int ch = t;                      // channel 0..127
    int hc = t >> 4;                 // head of this channel
    float acc = 0.f;
    for (int base = start; base < end; base += 16) {
        int j = base + q;
        if (j < end) {
            int s = g_esrc[j];
            s_alpha[grp][t] = __expf(leaky(g_asrc1[s * 8 + h] + adst)) * inv_h;
            if (h == 0) s_src[grp][q] = s;
        }
        asm volatile("bar.sync %0, 128;" :: "r"(grp + 1) : "memory");
        int cnt = min(16, end - base);
        #pragma unroll 4
        for (int qq = 0; qq < cnt; qq++) {
            int s = s_src[grp][qq];
            float a = s_alpha[grp][qq * 8 + hc];
            acc = fmaf(a, __bfloat162float(g_h1b[(size_t)s * F1 + ch]), acc);
        }
        asm volatile("bar.sync %0, 128;" :: "r"(grp + 1) : "memory");
    }
    float v = acc + b1[ch];
    v = v > 0.f ? v : (__expf(v) - 1.f);
    g_x2b[(size_t)n * F1 + ch] = __float2bfloat16(v);
}

// ---------------- GEMM2: h2 = x2 @ W2 (50000x128x64pad, bf16) ----------------
#define G2_SBUF (192 * SSTR)
__global__ __launch_bounds__(256, 2) void k_gemm2() {
    __shared__ uint32_t S[2][G2_SBUF];
    int tid = threadIdx.x;
    int lane = tid & 31;
    int warp = tid >> 5;
    int wm = warp >> 1;            // 0..3 : 32 rows
    int wn = warp & 1;             // 0..1 : 32 cols
    int g = lane >> 2;
    int t4 = lane & 3;
    int rowBase = blockIdx.x * 128;

    uint32_t sbase = (uint32_t)__cvta_generic_to_shared(&S[0][0]);

    auto stage_load = [&](int buf, int k0) {
        uint32_t b0 = sbase + (uint32_t)buf * (G2_SBUF * 4);
        #pragma unroll
        for (int i = 0; i < 3; i++) {
            int idx = tid + i * 256;      // 0..767
            int row = idx >> 2;           // 0..191
            int c = idx & 3;
            const void* src;
            int bytes = 16;
            if (row < 128) {
                int grow = rowBase + row;
                src = (grow < NN) ? (const void*)&g_x2b[(size_t)grow * F1 + k0 + c * 8]
                                  : (const void*)g_x2b;
                if (grow >= NN) bytes = 0;
            } else {
                src = &g_w2t[(size_t)(row - 128) * F1 + k0 + c * 8];
            }
            cp16(b0 + (row * SSTR + c * 4) * 4, src, bytes);
        }
    };

    float acc[2][4][4];
    #pragma unroll
    for (int mt = 0; mt < 2; mt++)
        #pragma unroll
        for (int nt = 0; nt < 4; nt++)
            #pragma unroll
            for (int i = 0; i < 4; i++) acc[mt][nt][i] = 0.f;

    stage_load(0, 0);
    cp_commit();

    #pragma unroll 1
    for (int it = 0; it < F1 / G1_BK; it++) {     // 4 iterations
        int buf = it & 1;
        if (it + 1 < F1 / G1_BK) {
            stage_load(buf ^ 1, (it + 1) * G1_BK);
            cp_commit();
            cp_wait<1>();
        } else {
            cp_wait<0>();
        }
        __syncthreads();

        const uint32_t* Sb = &S[buf][0];
        #pragma unroll
        for (int ks = 0; ks < 2; ks++) {
            uint32_t a[2][4];
            #pragma unroll
            for (int mt = 0; mt < 2; mt++) {
                int r0 = (wm * 32 + mt * 16 + g) * SSTR + ks * 8 + t4;
                a[mt][0] = Sb[r0];
                a[mt][1] = Sb[r0 + 8 * SSTR];
                a[mt][2] = Sb[r0 + 4];
                a[mt][3] = Sb[r0 + 8 * SSTR + 4];
            }
            #pragma unroll
            for (int nt = 0; nt < 4; nt++) {
                int bi = (128 + wn * 32 + nt * 8 + g) * SSTR + ks * 8 + t4;
                uint32_t b[2] = {Sb[bi], Sb[bi + 4]};
                mma_bf16(acc[0][nt], a[0], b);
                mma_bf16(acc[1][nt], a[1], b);
            }
        }
        __syncthreads();
    }

    // epilogue: write h2 f32 (cols < 40 only)
    #pragma unroll
    for (int mt = 0; mt < 2; mt++) {
        int row = rowBase + wm * 32 + mt * 16 + g;
        #pragma unroll
        for (int nt = 0; nt < 4; nt++) {
            int col = wn * 32 + nt * 8 + 2 * t4;
            if (col < F2) {
                if (row < NN)
                    *(float2*)&g_h2[(size_t)row * F2 + col] =
                        make_float2(acc[mt][nt][0], acc[mt][nt][1]);
                if (row + 8 < NN)
                    *(float2*)&g_h2[(size_t)(row + 8) * F2 + col] =
                        make_float2(acc[mt][nt][2], acc[mt][nt][3]);
            }
        }
    }
}

// ---------------- layer-2 attention coefficients -----------------------------
__global__ __launch_bounds__(256) void k_attc2(const float* __restrict__ att_src2,
                                               const float* __restrict__ att_dst2) {
    int warpId = (blockIdx.x * blockDim.x + threadIdx.x) >> 5;
    int lane = threadIdx.x & 31;
    if (warpId >= NN) return;
    const float* hr = &g_h2[(size_t)warpId * F2];
    float v0 = hr[lane];
    float v1 = (lane < 8) ? hr[32 + lane] : 0.f;
    float ps = v0 * att_src2[lane] + ((lane < 8) ? v1 * att_src2[32 + lane] : 0.f);
    float pd = v0 * att_dst2[lane] + ((lane < 8) ? v1 * att_dst2[32 + lane] : 0.f);
    #pragma unroll
    for (int off = 16; off > 0; off >>= 1) {
        ps += __shfl_xor_sync(0xffffffffu, ps, off);
        pd += __shfl_xor_sync(0xffffffffu, pd, off);
    }
    if (lane == 0) { g_asrc2[warpId] = ps; g_adst2[warpId] = pd; }
}

// ---------------- layer-2 aggregate + log_softmax ----------------------------
__global__ __launch_bounds__(256) void k_agg2(const float* __restrict__ b2,
                                              float* __restrict__ out) {
    int warpId = (blockIdx.x * blockDim.x + threadIdx.x) >> 5;
    int lane = threadIdx.x & 31;
    if (warpId >= NN) return;
    int n = warpId;
    int start = g_rowptr[n], end = g_rowptr[n + 1];
    float adst = g_adst2[n];

    float dsum = 0.f;
    for (int j = start + lane; j < end; j += 32)
        dsum += __expf(leaky(g_asrc2[g_esrc[j]] + adst));
    #pragma unroll
    for (int off = 16; off > 0; off >>= 1)
        dsum += __shfl_xor_sync(0xffffffffu, dsum, off);
    float inv = 1.f / (dsum + 1e-16f);

    float acc0 = 0.f, acc1 = 0.f;
    for (int base = start; base < end; base += 32) {
        int cnt = min(32, end - base);
        int s = 0;
        float al = 0.f;
        if (lane < cnt) {
            s = g_esrc[base + lane];
            al = __expf(leaky(g_asrc2[s] + adst));
        }
        for (int qq = 0; qq < cnt; qq++) {
            int sq = __shfl_sync(0xffffffffu, s, qq);
            float aq = __shfl_sync(0xffffffffu, al, qq) * inv;
            const float* hr = &g_h2[(size_t)sq * F2];
            acc0 = fmaf(hr[lane], aq, acc0);
            if (lane < 8) acc1 = fmaf(hr[32 + lane], aq, acc1);
        }
    }
    float v0 = acc0 + b2[lane];
    float v1 = (lane < 8) ? (acc1 + b2[32 + lane]) : -INFINITY;

    float mx = fmaxf(v0, v1);
    #pragma unroll
    for (int off = 16; off > 0; off >>= 1)
        mx = fmaxf(mx, __shfl_xor_sync(0xffffffffu, mx, off));
    float se = __expf(v0 - mx) + ((lane < 8) ? __expf(v1 - mx) : 0.f);
    #pragma unroll
    for (int off = 16; off > 0; off >>= 1)
        se += __shfl_xor_sync(0xffffffffu, se, off);
    float lse = mx + logf(se);

    float* o = &out[(size_t)n * F2];
    o[lane] = v0 - lse;
    if (lane < 8) o[32 + lane] = v1 - lse;
}

// ---------------- launch ------------------------------------------------------
extern "C" void kernel_launch(void* const* d_in, const int* in_sizes, int n_in,
                              void* d_out, int out_size) {
    const float* x   = (const float*)d_in[0];
    const int*   ei  = (const int*)d_in[1];
    const float* W1  = (const float*)d_in[2];
    const float* as1 = (const float*)d_in[3];
    const float* ad1 = (const float*)d_in[4];
    const float* b1  = (const float*)d_in[5];
    const float* W2  = (const float*)d_in[6];
    const float* as2 = (const float*)d_in[7];
    const float* ad2 = (const float*)d_in[8];
    const float* b2  = (const float*)d_in[9];
    float* out = (float*)d_out;

    k_convw<<<(F1 * FIN + 255) / 256, 256>>>(W1, W2);
    k_convx<<<(NN * FIN / 4 + 255) / 256, 256>>>(x);
    k_init<<<(NN + 255) / 256, 256>>>(ei);
    k_gemm1<<<(NN + G1_BM - 1) / G1_BM, 256>>>();
    k_hist<<<(EE + 255) / 256, 256>>>(ei);
    k_scan<<<1, SCAN_T>>>();
    k_scatter<<<(EE + NN + 255) / 256, 256>>>(ei);

    k_attc1<<<(NN * H1 + 255) / 256, 256>>>(as1, ad1);
    k_agg1<<<NN / 2, 256>>>(b1);

    k_gemm2<<<(NN + 127) / 128, 256>>>();
    k_attc2<<<(NN + 7) / 8, 256>>>(as2, ad2);
    k_agg2<<<(NN + 7) / 8, 256>>>(b2, out);
}

// round 7
// speedup vs baseline: 1.2805x; 1.2805x over previous
#include <cuda_runtime.h>
#include <cuda_bf16.h>
#include <math.h>
#include <stdint.h>

#define NN 50000
#define EE 800000
#define TOT (EE + NN)
#define FIN 512
#define F1 128      // H1*C1
#define H1 8
#define C1 16
#define F2 40       // H2*C2 = num classes
#define NEG 0.2f

// ---------------- scratch (device globals; no allocation allowed) ------------
__device__ __nv_bfloat16 g_xb[NN * FIN];      // x in bf16
__device__ __nv_bfloat16 g_w1t[F1 * FIN];     // W1^T bf16 (n-major, k contiguous)
__device__ __nv_bfloat16 g_w2t[64 * F1];      // W2^T bf16 padded to 64 cols
__device__ __nv_bfloat16 g_h1b[NN * F1];      // layer1 features bf16
__device__ __nv_bfloat16 g_x2b[NN * F1];      // elu(agg1+b1) bf16
__device__ float g_asrc1[NN * H1];
__device__ float g_adst1[NN * H1];
__device__ float g_alpha1[TOT * H1];          // exp(leaky(e)) per (edge,head), CSR order
__device__ float g_alpha2[TOT];               // layer-2 ditto
__device__ float g_h2[NN * F2];
__device__ float g_asrc2[NN];
__device__ float g_adst2[NN];
__device__ int   g_counts[NN];
__device__ int   g_rowptr[NN + 1];
__device__ int   g_cursor[NN];
__device__ int   g_esrc[TOT];                 // CSR-by-dst: src index
__device__ int   g_edst[TOT];                 // CSR-by-dst: dst index
__device__ int   g_is64;

// ---------------- input conversion -------------------------------------------
__global__ void k_convw(const float* __restrict__ W1, const float* __restrict__ W2) {
    int i = blockIdx.x * blockDim.x + threadIdx.x;
    if (i < F1 * FIN) {                          // W1^T
        int n = i >> 9, k = i & 511;
        g_w1t[i] = __float2bfloat16(W1[k * F1 + n]);
    }
    if (i < 64 * F1) {                           // W2^T (pad cols 40..63 with 0)
        int n = i >> 7, k = i & 127;
        g_w2t[i] = __float2bfloat16(n < F2 ? W2[k * F2 + n] : 0.f);
    }
}

__global__ void k_convx(const float* __restrict__ x) {
    int i = blockIdx.x * blockDim.x + threadIdx.x;   // per float4
    if (i >= NN * FIN / 4) return;
    float4 v = ((const float4*)x)[i];
    __nv_bfloat162 p0 = __floats2bfloat162_rn(v.x, v.y);
    __nv_bfloat162 p1 = __floats2bfloat162_rn(v.z, v.w);
    uint2 o;
    o.x = *(uint32_t*)&p0;
    o.y = *(uint32_t*)&p1;
    ((uint2*)g_xb)[i] = o;
}

// ---------------- CSR build --------------------------------------------------
__global__ void k_init(const int* __restrict__ ei32) {
    int i = blockIdx.x * blockDim.x + threadIdx.x;
    if (i < NN) g_counts[i] = 1;   // self-loop
    if (i == 0) {
        int z = 0;
        #pragma unroll 1
        for (int t = 0; t < 64; t++) if (ei32[2 * t + 1] == 0) z++;
        g_is64 = (z == 64) ? 1 : 0;
    }
}

__device__ __forceinline__ int edge_at(const int* ei32, int idx, int is64) {
    return is64 ? ei32[2 * idx] : ei32[idx];
}

__global__ void k_hist(const int* __restrict__ ei32) {
    int i = blockIdx.x * blockDim.x + threadIdx.x;
    if (i >= EE) return;
    int is64 = g_is64;
    int dd = edge_at(ei32, EE + i, is64);
    atomicAdd(&g_counts[dd], 1);
}

#define SCAN_T 1024
#define SCAN_CH ((NN + SCAN_T - 1) / SCAN_T)
__global__ void k_scan() {
    __shared__ int sums[SCAN_T];
    int t = threadIdx.x;
    int b0 = t * SCAN_CH;
    int b1 = min(b0 + SCAN_CH, NN);
    int s = 0;
    for (int i = b0; i < b1; i++) s += g_counts[i];
    sums[t] = s;
    __syncthreads();
    for (int off = 1; off < SCAN_T; off <<= 1) {
        int v = (t >= off) ? sums[t - off] : 0;
        __syncthreads();
        sums[t] += v;
        __syncthreads();
    }
    int offset = (t == 0) ? 0 : sums[t - 1];
    for (int i = b0; i < b1; i++) {
        g_rowptr[i] = offset;
        g_cursor[i] = offset;
        offset += g_counts[i];
    }
    if (t == 0) g_rowptr[NN] = sums[SCAN_T - 1];
}

__global__ void k_scatter(const int* __restrict__ ei32) {
    int i = blockIdx.x * blockDim.x + threadIdx.x;
    if (i >= TOT) return;
    int is64 = g_is64;
    int s, dd;
    if (i < EE) { s = edge_at(ei32, i, is64); dd = edge_at(ei32, EE + i, is64); }
    else        { s = dd = i - EE; }
    int pos = atomicAdd(&g_cursor[dd], 1);
    g_esrc[pos] = s;
    g_edst[pos] = dd;
}

// ---------------- shared GEMM helpers ----------------------------------------
#define SSTR 20             // u32 stride per row (16 used, pad to 20: conflict-free)

__device__ __forceinline__ void cp16(uint32_t dst, const void* src, int bytes) {
    asm volatile("cp.async.cg.shared.global [%0], [%1], 16, %2;"
                 :: "r"(dst), "l"(src), "r"(bytes));
}
__device__ __forceinline__ void cp_commit() {
    asm volatile("cp.async.commit_group;");
}
template <int N> __device__ __forceinline__ void cp_wait() {
    asm volatile("cp.async.wait_group %0;" :: "n"(N));
}

__device__ __forceinline__ void mma_bf16(float c[4], const uint32_t a[4],
                                         const uint32_t b[2]) {
    asm volatile(
        "mma.sync.aligned.m16n8k16.row.col.f32.bf16.bf16.f32 "
        "{%0,%1,%2,%3}, {%4,%5,%6,%7}, {%8,%9}, {%0,%1,%2,%3};"
        : "+f"(c[0]), "+f"(c[1]), "+f"(c[2]), "+f"(c[3])
        : "r"(a[0]), "r"(a[1]), "r"(a[2]), "r"(a[3]), "r"(b[0]), "r"(b[1]));
}

// ---------------- GEMM1: h1 = x @ W1  (50000x512x128, bf16) ------------------
#define G1_BM 128
#define G1_BK 32
#define SBUF (256 * SSTR)   // one stage: 128 A-rows + 128 B-cols

__global__ __launch_bounds__(256, 2) void k_gemm1() {
    __shared__ uint32_t S[2][SBUF];
    int tid = threadIdx.x;
    int lane = tid & 31;
    int warp = tid >> 5;
    int wm = warp >> 1;            // 0..3 : 32 rows each
    int wn = warp & 1;             // 0..1 : 64 cols each
    int g = lane >> 2;             // 0..7
    int t4 = lane & 3;             // 0..3
    int rowBase = blockIdx.x * G1_BM;

    uint32_t sbase = (uint32_t)__cvta_generic_to_shared(&S[0][0]);
    int lr = tid >> 2;             // 0..63
    int lc = tid & 3;              // 0..3 (16B chunk)

    auto stage_load = [&](int buf, int k0) {
        uint32_t b0 = sbase + (uint32_t)buf * (SBUF * 4);
        #pragma unroll
        for (int l = 0; l < 128; l += 64) {
            int row = rowBase + lr + l;
            const void* pa = (row < NN) ? (const void*)&g_xb[(size_t)row * FIN + k0 + lc * 8]
                                        : (const void*)g_xb;
            cp16(b0 + ((lr + l) * SSTR + lc * 4) * 4, pa, (row < NN) ? 16 : 0);
            cp16(b0 + ((128 + lr + l) * SSTR + lc * 4) * 4,
                 &g_w1t[(size_t)(lr + l) * FIN + k0 + lc * 8], 16);
        }
    };

    float acc[2][8][4];
    #pragma unroll
    for (int mt = 0; mt < 2; mt++)
        #pragma unroll
        for (int nt = 0; nt < 8; nt++)
            #pragma unroll
            for (int i = 0; i < 4; i++) acc[mt][nt][i] = 0.f;

    stage_load(0, 0);
    cp_commit();

    #pragma unroll 1
    for (int it = 0; it < FIN / G1_BK; it++) {
        int buf = it & 1;
        if (it + 1 < FIN / G1_BK) {
            stage_load(buf ^ 1, (it + 1) * G1_BK);
            cp_commit();
            cp_wait<1>();
        } else {
            cp_wait<0>();
        }
        __syncthreads();

        const uint32_t* Sb = &S[buf][0];
        #pragma unroll
        for (int ks = 0; ks < 2; ks++) {
            uint32_t a[2][4];
            #pragma unroll
            for (int mt = 0; mt < 2; mt++) {
                int r0 = (wm * 32 + mt * 16 + g) * SSTR + ks * 8 + t4;
                a[mt][0] = Sb[r0];
                a[mt][1] = Sb[r0 + 8 * SSTR];
                a[mt][2] = Sb[r0 + 4];
                a[mt][3] = Sb[r0 + 8 * SSTR + 4];
            }
            #pragma unroll
            for (int nt = 0; nt < 8; nt++) {
                int bi = (128 + wn * 64 + nt * 8 + g) * SSTR + ks * 8 + t4;
                uint32_t b[2] = {Sb[bi], Sb[bi + 4]};
                mma_bf16(acc[0][nt], a[0], b);
                mma_bf16(acc[1][nt], a[1], b);
            }
        }
        __syncthreads();
    }

    // epilogue: write h1 as bf16
    #pragma unroll
    for (int mt = 0; mt < 2; mt++) {
        int row = rowBase + wm * 32 + mt * 16 + g;
        #pragma unroll
        for (int nt = 0; nt < 8; nt++) {
            int col = wn * 64 + nt * 8 + 2 * t4;
            if (row < NN)
                *(__nv_bfloat162*)&g_h1b[(size_t)row * F1 + col] =
                    __floats2bfloat162_rn(acc[mt][nt][0], acc[mt][nt][1]);
            if (row + 8 < NN)
                *(__nv_bfloat162*)&g_h1b[(size_t)(row + 8) * F1 + col] =
                    __floats2bfloat162_rn(acc[mt][nt][2], acc[mt][nt][3]);
        }
    }
}

// ---------------- layer-1 attention coefficients -----------------------------
__global__ void k_attc1(const float* __restrict__ att_src1,
                        const float* __restrict__ att_dst1) {
    int idx = blockIdx.x * blockDim.x + threadIdx.x;   // n*8 + h
    if (idx >= NN * H1) return;
    int h = idx & 7;
    const __nv_bfloat16* hp = &g_h1b[(size_t)(idx >> 3) * F1 + h * C1];
    float s = 0.f, t = 0.f;
    #pragma unroll
    for (int c = 0; c < C1; c++) {
        float v = __bfloat162float(hp[c]);
        s = fmaf(v, att_src1[h * C1 + c], s);
        t = fmaf(v, att_dst1[h * C1 + c], t);
    }
    g_asrc1[idx] = s;
    g_adst1[idx] = t;
}

__device__ __forceinline__ float leaky(float e) { return e > 0.f ? e : NEG * e; }

// ---------------- edge exp, layer 1 (per edge,head; CSR order) ---------------
__global__ void k_edgee1() {
    int i = blockIdx.x * blockDim.x + threadIdx.x;   // j*8 + h
    if (i >= TOT * H1) return;
    int j = i >> 3, h = i & 7;
    int s = g_esrc[j], d = g_edst[j];
    g_alpha1[i] = __expf(leaky(g_asrc1[s * H1 + h] + g_adst1[d * H1 + h]));
}

// ---------------- layer-1 aggregate (warp per node; alpha precomputed) -------
__global__ __launch_bounds__(256) void k_agg1(const float* __restrict__ b1) {
    int warpId = (blockIdx.x * blockDim.x + threadIdx.x) >> 5;
    int lane = threadIdx.x & 31;
    if (warpId >= NN) return;
    int n = warpId;
    int start = g_rowptr[n], end = g_rowptr[n + 1];

    // pass 1: per-head denominator — sequential coalesced sweep over alpha1
    float part = 0.f;
    for (int f = start * 8 + lane; f < end * 8; f += 32)
        part += g_alpha1[f];                 // head of this lane = lane & 7 (fixed)
    part += __shfl_xor_sync(0xffffffffu, part, 8);
    part += __shfl_xor_sync(0xffffffffu, part, 16);
    float inv = 1.f / (part + 1e-16f);       // valid on lanes 0..7 (head = lane)

    int hb = lane >> 4;                      // head of channel `lane`
    float inv0 = __shfl_sync(0xffffffffu, inv, hb);
    float inv1 = __shfl_sync(0xffffffffu, inv, hb + 2);
    float inv2 = __shfl_sync(0xffffffffu, inv, hb + 4);
    float inv3 = __shfl_sync(0xffffffffu, inv, hb + 6);

    // pass 2: gather h1b rows weighted by raw alpha (normalize at the end)
    float acc0 = 0.f, acc1 = 0.f, acc2 = 0.f, acc3 = 0.f;
    for (int j = start; j < end; j++) {
        int s = g_esrc[j];
        const float* al = &g_alpha1[j * 8];
        float a0 = al[hb], a1 = al[hb + 2], a2 = al[hb + 4], a3 = al[hb + 6];
        const __nv_bfloat16* hr = &g_h1b[(size_t)s * F1];
        acc0 = fmaf(a0, __bfloat162float(hr[lane]),      acc0);
        acc1 = fmaf(a1, __bfloat162float(hr[lane + 32]), acc1);
        acc2 = fmaf(a2, __bfloat162float(hr[lane + 64]), acc2);
        acc3 = fmaf(a3, __bfloat162float(hr[lane + 96]), acc3);
    }
    __nv_bfloat16* o = &g_x2b[(size_t)n * F1];
    float v;
    v = acc0 * inv0 + b1[lane];      v = v > 0.f ? v : (__expf(v) - 1.f); o[lane]      = __float2bfloat16(v);
    v = acc1 * inv1 + b1[lane + 32]; v = v > 0.f ? v : (__expf(v) - 1.f); o[lane + 32] = __float2bfloat16(v);
    v = acc2 * inv2 + b1[lane + 64]; v = v > 0.f ? v : (__expf(v) - 1.f); o[lane + 64] = __float2bfloat16(v);
    v = acc3 * inv3 + b1[lane + 96]; v = v > 0.f ? v : (__expf(v) - 1.f); o[lane + 96] = __float2bfloat16(v);
}

// ---------------- GEMM2: h2 = x2 @ W2 (50000x128x64pad, bf16) ----------------
#define G2_SBUF (192 * SSTR)
__global__ __launch_bounds__(256, 2) void k_gemm2() {
    __shared__ uint32_t S[2][G2_SBUF];
    int tid = threadIdx.x;
    int lane = tid & 31;
    int warp = tid >> 5;
    int wm = warp >> 1;            // 0..3 : 32 rows
    int wn = warp & 1;             // 0..1 : 32 cols
    int g = lane >> 2;
    int t4 = lane & 3;
    int rowBase = blockIdx.x * 128;

    uint32_t sbase = (uint32_t)__cvta_generic_to_shared(&S[0][0]);

    auto stage_load = [&](int buf, int k0) {
        uint32_t b0 = sbase + (uint32_t)buf * (G2_SBUF * 4);
        #pragma unroll
        for (int i = 0; i < 3; i++) {
            int idx = tid + i * 256;      // 0..767
            int row = idx >> 2;           // 0..191
            int c = idx & 3;
            const void* src;
            int bytes = 16;
            if (row < 128) {
                int grow = rowBase + row;
                src = (grow < NN) ? (const void*)&g_x2b[(size_t)grow * F1 + k0 + c * 8]
                                  : (const void*)g_x2b;
                if (grow >= NN) bytes = 0;
            } else {
                src = &g_w2t[(size_t)(row - 128) * F1 + k0 + c * 8];
            }
            cp16(b0 + (row * SSTR + c * 4) * 4, src, bytes);
        }
    };

    float acc[2][4][4];
    #pragma unroll
    for (int mt = 0; mt < 2; mt++)
        #pragma unroll
        for (int nt = 0; nt < 4; nt++)
            #pragma unroll
            for (int i = 0; i < 4; i++) acc[mt][nt][i] = 0.f;

    stage_load(0, 0);
    cp_commit();

    #pragma unroll 1
    for (int it = 0; it < F1 / G1_BK; it++) {     // 4 iterations
        int buf = it & 1;
        if (it + 1 < F1 / G1_BK) {
            stage_load(buf ^ 1, (it + 1) * G1_BK);
            cp_commit();
            cp_wait<1>();
        } else {
            cp_wait<0>();
        }
        __syncthreads();

        const uint32_t* Sb = &S[buf][0];
        #pragma unroll
        for (int ks = 0; ks < 2; ks++) {
            uint32_t a[2][4];
            #pragma unroll
            for (int mt = 0; mt < 2; mt++) {
                int r0 = (wm * 32 + mt * 16 + g) * SSTR + ks * 8 + t4;
                a[mt][0] = Sb[r0];
                a[mt][1] = Sb[r0 + 8 * SSTR];
                a[mt][2] = Sb[r0 + 4];
                a[mt][3] = Sb[r0 + 8 * SSTR + 4];
            }
            #pragma unroll
            for (int nt = 0; nt < 4; nt++) {
                int bi = (128 + wn * 32 + nt * 8 + g) * SSTR + ks * 8 + t4;
                uint32_t b[2] = {Sb[bi], Sb[bi + 4]};
                mma_bf16(acc[0][nt], a[0], b);
                mma_bf16(acc[1][nt], a[1], b);
            }
        }
        __syncthreads();
    }

    // epilogue: write h2 f32 (cols < 40 only)
    #pragma unroll
    for (int mt = 0; mt < 2; mt++) {
        int row = rowBase + wm * 32 + mt * 16 + g;
        #pragma unroll
        for (int nt = 0; nt < 4; nt++) {
            int col = wn * 32 + nt * 8 + 2 * t4;
            if (col < F2) {
                if (row < NN)
                    *(float2*)&g_h2[(size_t)row * F2 + col] =
                        make_float2(acc[mt][nt][0], acc[mt][nt][1]);
                if (row + 8 < NN)
                    *(float2*)&g_h2[(size_t)(row + 8) * F2 + col] =
                        make_float2(acc[mt][nt][2], acc[mt][nt][3]);
            }
        }
    }
}

// ---------------- layer-2 attention coefficients -----------------------------
__global__ __launch_bounds__(256) void k_attc2(const float* __restrict__ att_src2,
                                               const float* __restrict__ att_dst2) {
    int warpId = (blockIdx.x * blockDim.x + threadIdx.x) >> 5;
    int lane = threadIdx.x & 31;
    if (warpId >= NN) return;
    const float* hr = &g_h2[(size_t)warpId * F2];
    float v0 = hr[lane];
    float v1 = (lane < 8) ? hr[32 + lane] : 0.f;
    float ps = v0 * att_src2[lane] + ((lane < 8) ? v1 * att_src2[32 + lane] : 0.f);
    float pd = v0 * att_dst2[lane] + ((lane < 8) ? v1 * att_dst2[32 + lane] : 0.f);
    #pragma unroll
    for (int off = 16; off > 0; off >>= 1) {
        ps += __shfl_xor_sync(0xffffffffu, ps, off);
        pd += __shfl_xor_sync(0xffffffffu, pd, off);
    }
    if (lane == 0) { g_asrc2[warpId] = ps; g_adst2[warpId] = pd; }
}

// ---------------- edge exp, layer 2 ------------------------------------------
__global__ void k_edgee2() {
    int j = blockIdx.x * blockDim.x + threadIdx.x;
    if (j >= TOT) return;
    int s = g_esrc[j], d = g_edst[j];
    g_alpha2[j] = __expf(leaky(g_asrc2[s] + g_adst2[d]));
}

// ---------------- layer-2 aggregate + log_softmax ----------------------------
__global__ __launch_bounds__(256) void k_agg2(const float* __restrict__ b2,
                                              float* __restrict__ out) {
    int warpId = (blockIdx.x * blockDim.x + threadIdx.x) >> 5;
    int lane = threadIdx.x & 31;
    if (warpId >= NN) return;
    int n = warpId;
    int start = g_rowptr[n], end = g_rowptr[n + 1];

    // pass 1: denominator — sequential coalesced sweep
    float dsum = 0.f;
    for (int j = start + lane; j < end; j += 32)
        dsum += g_alpha2[j];
    #pragma unroll
    for (int off = 16; off > 0; off >>= 1)
        dsum += __shfl_xor_sync(0xffffffffu, dsum, off);
    float inv = 1.f / (dsum + 1e-16f);

    // pass 2: gather (raw alpha; normalize at end)
    float acc0 = 0.f, acc1 = 0.f;
    for (int j = start; j < end; j++) {
        int s = g_esrc[j];
        float aq = g_alpha2[j];
        const float* hr = &g_h2[(size_t)s * F2];
        acc0 = fmaf(hr[lane], aq, acc0);
        if (lane < 8) acc1 = fmaf(hr[32 + lane], aq, acc1);
    }
    float v0 = acc0 * inv + b2[lane];
    float v1 = (lane < 8) ? (acc1 * inv + b2[32 + lane]) : -INFINITY;

    float mx = fmaxf(v0, v1);
    #pragma unroll
    for (int off = 16; off > 0; off >>= 1)
        mx = fmaxf(mx, __shfl_xor_sync(0xffffffffu, mx, off));
    float se = __expf(v0 - mx) + ((lane < 8) ? __expf(v1 - mx) : 0.f);
    #pragma unroll
    for (int off = 16; off > 0; off >>= 1)
        se += __shfl_xor_sync(0xffffffffu, se, off);
    float lse = mx + logf(se);

    float* o = &out[(size_t)n * F2];
    o[lane] = v0 - lse;
    if (lane < 8) o[32 + lane] = v1 - lse;
}

// ---------------- launch ------------------------------------------------------
extern "C" void kernel_launch(void* const* d_in, const int* in_sizes, int n_in,
                              void* d_out, int out_size) {
    const float* x   = (const float*)d_in[0];
    const int*   ei  = (const int*)d_in[1];
    const float* W1  = (const float*)d_in[2];
    const float* as1 = (const float*)d_in[3];
    const float* ad1 = (const float*)d_in[4];
    const float* b1  = (const float*)d_in[5];
    const float* W2  = (const float*)d_in[6];
    const float* as2 = (const float*)d_in[7];
    const float* ad2 = (const float*)d_in[8];
    const float* b2  = (const float*)d_in[9];
    float* out = (float*)d_out;

    k_convw<<<(F1 * FIN + 255) / 256, 256>>>(W1, W2);
    k_init<<<(NN + 255) / 256, 256>>>(ei);
    k_hist<<<(EE + 255) / 256, 256>>>(ei);
    k_convx<<<(NN * FIN / 4 + 255) / 256, 256>>>(x);   // 4th launch → profiled
    k_scan<<<1, SCAN_T>>>();
    k_scatter<<<(TOT + 255) / 256, 256>>>(ei);

    k_gemm1<<<(NN + G1_BM - 1) / G1_BM, 256>>>();
    k_attc1<<<(NN * H1 + 255) / 256, 256>>>(as1, ad1);
    k_edgee1<<<(TOT * H1 + 255) / 256, 256>>>();
    k_agg1<<<(NN + 7) / 8, 256>>>(b1);

    k_gemm2<<<(NN + 127) / 128, 256>>>();
    k_attc2<<<(NN + 7) / 8, 256>>>(as2, ad2);
    k_edgee2<<<(TOT + 255) / 256, 256>>>();
    k_agg2<<<(NN + 7) / 8, 256>>>(b2, out);
}

// round 8
// speedup vs baseline: 1.4650x; 1.1441x over previous
#include <cuda_runtime.h>
#include <cuda_bf16.h>
#include <math.h>
#include <stdint.h>

#define NN 50000
#define EE 800000
#define TOT (EE + NN)
#define FIN 512
#define F1 128      // H1*C1
#define H1 8
#define C1 16
#define F2 40       // H2*C2 = num classes
#define NEG 0.2f

// ---------------- scratch (device globals; no allocation allowed) ------------
__device__ __nv_bfloat16 g_w1t[F1 * FIN];     // W1^T bf16 (n-major, k contiguous)
__device__ __nv_bfloat16 g_w2t[64 * F1];      // W2^T bf16 padded to 64 cols
__device__ __nv_bfloat16 g_h1b[NN * F1];      // layer1 features bf16
__device__ __nv_bfloat16 g_x2b[NN * F1];      // elu(agg1+b1) bf16
__device__ float g_asrc1[NN * H1];
__device__ float g_adst1[NN * H1];
__device__ float g_alpha1[TOT * H1];          // exp(leaky(e)) per (edge,head), CSR order
__device__ float g_alpha2[TOT];               // layer-2 ditto
__device__ float g_h2[NN * F2];
__device__ float g_asrc2[NN];
__device__ float g_adst2[NN];
__device__ int   g_counts[NN];
__device__ int   g_rowptr[NN + 1];
__device__ int   g_cursor[NN];
__device__ int   g_esrc[TOT];                 // CSR-by-dst: src index
__device__ int   g_edst[TOT];                 // CSR-by-dst: dst index
__device__ int   g_is64;

// ---------------- weight conversion + init -----------------------------------
__global__ void k_convw(const float* __restrict__ W1, const float* __restrict__ W2,
                        const int* __restrict__ ei32) {
    int i = blockIdx.x * blockDim.x + threadIdx.x;
    if (i < F1 * FIN) {                          // W1^T
        int n = i >> 9, k = i & 511;
        g_w1t[i] = __float2bfloat16(W1[k * F1 + n]);
    }
    if (i < 64 * F1) {                           // W2^T (pad cols 40..63 with 0)
        int n = i >> 7, k = i & 127;
        g_w2t[i] = __float2bfloat16(n < F2 ? W2[k * F2 + n] : 0.f);
    }
    if (i < NN) g_counts[i] = 1;                 // self-loop
    if (i == 0) {
        int z = 0;
        #pragma unroll 1
        for (int t = 0; t < 64; t++) if (ei32[2 * t + 1] == 0) z++;
        g_is64 = (z == 64) ? 1 : 0;
    }
}

// ---------------- CSR build --------------------------------------------------
__device__ __forceinline__ int edge_at(const int* ei32, int idx, int is64) {
    return is64 ? ei32[2 * idx] : ei32[idx];
}

__global__ void k_hist(const int* __restrict__ ei32) {
    int i = blockIdx.x * blockDim.x + threadIdx.x;
    if (i >= EE) return;
    int is64 = g_is64;
    int dd = edge_at(ei32, EE + i, is64);
    atomicAdd(&g_counts[dd], 1);
}

#define SCAN_T 1024
#define SCAN_CH ((NN + SCAN_T - 1) / SCAN_T)
__global__ void k_scan() {
    __shared__ int sums[SCAN_T];
    int t = threadIdx.x;
    int b0 = t * SCAN_CH;
    int b1 = min(b0 + SCAN_CH, NN);
    int s = 0;
    for (int i = b0; i < b1; i++) s += g_counts[i];
    sums[t] = s;
    __syncthreads();
    for (int off = 1; off < SCAN_T; off <<= 1) {
        int v = (t >= off) ? sums[t - off] : 0;
        __syncthreads();
        sums[t] += v;
        __syncthreads();
    }
    int offset = (t == 0) ? 0 : sums[t - 1];
    for (int i = b0; i < b1; i++) {
        g_rowptr[i] = offset;
        g_cursor[i] = offset;
        offset += g_counts[i];
    }
    if (t == 0) g_rowptr[NN] = sums[SCAN_T - 1];
}

__global__ void k_scatter(const int* __restrict__ ei32) {
    int i = blockIdx.x * blockDim.x + threadIdx.x;
    if (i >= TOT) return;
    int is64 = g_is64;
    int s, dd;
    if (i < EE) { s = edge_at(ei32, i, is64); dd = edge_at(ei32, EE + i, is64); }
    else        { s = dd = i - EE; }
    int pos = atomicAdd(&g_cursor[dd], 1);
    g_esrc[pos] = s;
    g_edst[pos] = dd;
}

// ---------------- shared GEMM helpers ----------------------------------------
#define SSTR 20             // u32 stride per row (16 used, pad to 20: conflict-free)

__device__ __forceinline__ void cp16(uint32_t dst, const void* src, int bytes) {
    asm volatile("cp.async.cg.shared.global [%0], [%1], 16, %2;"
                 :: "r"(dst), "l"(src), "r"(bytes));
}
__device__ __forceinline__ void cp_commit() {
    asm volatile("cp.async.commit_group;");
}
template <int N> __device__ __forceinline__ void cp_wait() {
    asm volatile("cp.async.wait_group %0;" :: "n"(N));
}

__device__ __forceinline__ void mma_bf16(float c[4], const uint32_t a[4],
                                         const uint32_t b[2]) {
    asm volatile(
        "mma.sync.aligned.m16n8k16.row.col.f32.bf16.bf16.f32 "
        "{%0,%1,%2,%3}, {%4,%5,%6,%7}, {%8,%9}, {%0,%1,%2,%3};"
        : "+f"(c[0]), "+f"(c[1]), "+f"(c[2]), "+f"(c[3])
        : "r"(a[0]), "r"(a[1]), "r"(a[2]), "r"(a[3]), "r"(b[0]), "r"(b[1]));
}

__device__ __forceinline__ uint32_t pack_bf16(float lo, float hi) {
    __nv_bfloat162 p = __floats2bfloat162_rn(lo, hi);
    return *(uint32_t*)&p;
}

// ---------------- GEMM1: h1 = x(f32) @ W1  (fused conversion) ----------------
#define G1_BM 128
#define G1_BK 32
#define SBUF (256 * SSTR)   // one stage: 128 A-rows + 128 B-cols

__global__ __launch_bounds__(256, 2) void k_gemm1(const float* __restrict__ x) {
    __shared__ uint32_t S[2][SBUF];
    int tid = threadIdx.x;
    int lane = tid & 31;
    int warp = tid >> 5;
    int wm = warp >> 1;            // 0..3 : 32 rows each
    int wn = warp & 1;             // 0..1 : 64 cols each
    int g = lane >> 2;             // 0..7
    int t4 = lane & 3;             // 0..3
    int rowBase = blockIdx.x * G1_BM;

    uint32_t sbase = (uint32_t)__cvta_generic_to_shared(&S[0][0]);

    // A (f32) load mapping: 1024 float4 per stage, 4 per thread
    int ar = tid >> 1;             // row pair base: idx = tid + l*256 → row = idx>>3
    (void)ar;
    // B cp.async mapping: 128 rows x 4 chunks = 512, 2 per thread
    int br = tid >> 1;             // 0..127
    int bc = tid & 1;              // chunk pair: covers c = bc*2, bc*2+1

    float4 av[4];
    auto a_load = [&](int k0) {
        #pragma unroll
        for (int l = 0; l < 4; l++) {
            int idx = tid + l * 256;
            int row = rowBase + (idx >> 3);
            int c4 = (idx & 7) << 2;
            av[l] = (row < NN) ? *(const float4*)&x[(size_t)row * FIN + k0 + c4]
                               : make_float4(0.f, 0.f, 0.f, 0.f);
        }
    };
    auto a_store = [&](int buf) {
        uint32_t* Sb = &S[buf][0];
        #pragma unroll
        for (int l = 0; l < 4; l++) {
            int idx = tid + l * 256;
            int row = idx >> 3;
            int c2 = (idx & 7) << 1;         // u32 pair offset
            Sb[row * SSTR + c2]     = pack_bf16(av[l].x, av[l].y);
            Sb[row * SSTR + c2 + 1] = pack_bf16(av[l].z, av[l].w);
        }
    };
    auto b_load = [&](int buf, int k0) {
        uint32_t b0 = sbase + (uint32_t)buf * (SBUF * 4);
        #pragma unroll
        for (int l = 0; l < 2; l++) {
            int c = bc * 2 + l;
            cp16(b0 + ((128 + br) * SSTR + c * 4) * 4,
                 &g_w1t[(size_t)br * FIN + k0 + c * 8], 16);
        }
    };

    float acc[2][8][4];
    #pragma unroll
    for (int mt = 0; mt < 2; mt++)
        #pragma unroll
        for (int nt = 0; nt < 8; nt++)
            #pragma unroll
            for (int i = 0; i < 4; i++) acc[mt][nt][i] = 0.f;

    a_load(0);
    b_load(0, 0);
    cp_commit();

    #pragma unroll 1
    for (int it = 0; it < FIN / G1_BK; it++) {
        int buf = it & 1;
        a_store(buf);
        if (it + 1 < FIN / G1_BK) {
            a_load((it + 1) * G1_BK);
            b_load(buf ^ 1, (it + 1) * G1_BK);
            cp_commit();
            cp_wait<1>();
        } else {
            cp_wait<0>();
        }
        __syncthreads();

        const uint32_t* Sb = &S[buf][0];
        #pragma unroll
        for (int ks = 0; ks < 2; ks++) {
            uint32_t a[2][4];
            #pragma unroll
            for (int mt = 0; mt < 2; mt++) {
                int r0 = (wm * 32 + mt * 16 + g) * SSTR + ks * 8 + t4;
                a[mt][0] = Sb[r0];
                a[mt][1] = Sb[r0 + 8 * SSTR];
                a[mt][2] = Sb[r0 + 4];
                a[mt][3] = Sb[r0 + 8 * SSTR + 4];
            }
            #pragma unroll
            for (int nt = 0; nt < 8; nt++) {
                int bi = (128 + wn * 64 + nt * 8 + g) * SSTR + ks * 8 + t4;
                uint32_t b[2] = {Sb[bi], Sb[bi + 4]};
                mma_bf16(acc[0][nt], a[0], b);
                mma_bf16(acc[1][nt], a[1], b);
            }
        }
        __syncthreads();
    }

    // epilogue: write h1 as bf16
    #pragma unroll
    for (int mt = 0; mt < 2; mt++) {
        int row = rowBase + wm * 32 + mt * 16 + g;
        #pragma unroll
        for (int nt = 0; nt < 8; nt++) {
            int col = wn * 64 + nt * 8 + 2 * t4;
            if (row < NN)
                *(__nv_bfloat162*)&g_h1b[(size_t)row * F1 + col] =
                    __floats2bfloat162_rn(acc[mt][nt][0], acc[mt][nt][1]);
            if (row + 8 < NN)
                *(__nv_bfloat162*)&g_h1b[(size_t)(row + 8) * F1 + col] =
                    __floats2bfloat162_rn(acc[mt][nt][2], acc[mt][nt][3]);
        }
    }
}

// ---------------- layer-1 attention coefficients -----------------------------
__global__ void k_attc1(const float* __restrict__ att_src1,
                        const float* __restrict__ att_dst1) {
    int idx = blockIdx.x * blockDim.x + threadIdx.x;   // n*8 + h
    if (idx >= NN * H1) return;
    int h = idx & 7;
    const __nv_bfloat16* hp = &g_h1b[(size_t)(idx >> 3) * F1 + h * C1];
    float s = 0.f, t = 0.f;
    #pragma unroll
    for (int c = 0; c < C1; c++) {
        float v = __bfloat162float(hp[c]);
        s = fmaf(v, att_src1[h * C1 + c], s);
        t = fmaf(v, att_dst1[h * C1 + c], t);
    }
    g_asrc1[idx] = s;
    g_adst1[idx] = t;
}

__device__ __forceinline__ float leaky(float e) { return e > 0.f ? e : NEG * e; }

// ---------------- edge exp, layer 1 (per edge,head; CSR order) ---------------
__global__ void k_edgee1() {
    int i = blockIdx.x * blockDim.x + threadIdx.x;   // j*8 + h
    if (i >= TOT * H1) return;
    int j = i >> 3, h = i & 7;
    int s = g_esrc[j], d = g_edst[j];
    g_alpha1[i] = __expf(leaky(g_asrc1[s * H1 + h] + g_adst1[d * H1 + h]));
}

// ---------------- layer-1 aggregate (warp per node; bf16x2 gather) -----------
__global__ __launch_bounds__(256) void k_agg1(const float* __restrict__ b1) {
    int warpId = (blockIdx.x * blockDim.x + threadIdx.x) >> 5;
    int lane = threadIdx.x & 31;
    if (warpId >= NN) return;
    int n = warpId;
    int start = g_rowptr[n], end = g_rowptr[n + 1];

    // pass 1: per-head denominator — sequential coalesced sweep over alpha1
    float part = 0.f;
    for (int f = start * 8 + lane; f < end * 8; f += 32)
        part += g_alpha1[f];
    part += __shfl_xor_sync(0xffffffffu, part, 8);
    part += __shfl_xor_sync(0xffffffffu, part, 16);
    float inv = 1.f / (part + 1e-16f);       // valid on lanes 0..7 (head = lane)

    // this lane owns bf162 pairs p0=lane (heads 0..3) and p1=lane+32 (heads 4..7)
    int h0 = lane >> 3;                      // head of pair p0
    float inv0 = __shfl_sync(0xffffffffu, inv, h0);
    float inv1 = __shfl_sync(0xffffffffu, inv, h0 + 4);

    // pass 2: gather h1b pairs weighted by raw alpha (normalize at the end)
    float2 acc0 = make_float2(0.f, 0.f), acc1 = make_float2(0.f, 0.f);
    for (int j = start; j < end; j++) {
        int s = g_esrc[j];
        const float* al = &g_alpha1[j * 8];
        float a0 = al[h0], a1 = al[h0 + 4];
        const __nv_bfloat162* hr = (const __nv_bfloat162*)&g_h1b[(size_t)s * F1];
        float2 v0 = __bfloat1622float2(hr[lane]);
        float2 v1 = __bfloat1622float2(hr[lane + 32]);
        acc0.x = fmaf(a0, v0.x, acc0.x); acc0.y = fmaf(a0, v0.y, acc0.y);
        acc1.x = fmaf(a1, v1.x, acc1.x); acc1.y = fmaf(a1, v1.y, acc1.y);
    }
    float2 b0 = ((const float2*)b1)[lane];
    float2 b64 = ((const float2*)b1)[lane + 32];
    __nv_bfloat162* o = (__nv_bfloat162*)&g_x2b[(size_t)n * F1];
    float vx, vy;
    vx = acc0.x * inv0 + b0.x;  vx = vx > 0.f ? vx : (__expf(vx) - 1.f);
    vy = acc0.y * inv0 + b0.y;  vy = vy > 0.f ? vy : (__expf(vy) - 1.f);
    o[lane] = __floats2bfloat162_rn(vx, vy);
    vx = acc1.x * inv1 + b64.x; vx = vx > 0.f ? vx : (__expf(vx) - 1.f);
    vy = acc1.y * inv1 + b64.y; vy = vy > 0.f ? vy : (__expf(vy) - 1.f);
    o[lane + 32] = __floats2bfloat162_rn(vx, vy);
}

// ---------------- GEMM2: h2 = x2 @ W2 (50000x128x64pad, bf16) ----------------
#define G2_SBUF (192 * SSTR)
__global__ __launch_bounds__(256, 2) void k_gemm2() {
    __shared__ uint32_t S[2][G2_SBUF];
    int tid = threadIdx.x;
    int lane = tid & 31;
    int warp = tid >> 5;
    int wm = warp >> 1;            // 0..3 : 32 rows
    int wn = warp & 1;             // 0..1 : 32 cols
    int g = lane >> 2;
    int t4 = lane & 3;
    int rowBase = blockIdx.x * 128;

    uint32_t sbase = (uint32_t)__cvta_generic_to_shared(&S[0][0]);

    auto stage_load = [&](int buf, int k0) {
        uint32_t b0 = sbase + (uint32_t)buf * (G2_SBUF * 4);
        #pragma unroll
        for (int i = 0; i < 3; i++) {
            int idx = tid + i * 256;      // 0..767
            int row = idx >> 2;           // 0..191
            int c = idx & 3;
            const void* src;
            int bytes = 16;
            if (row < 128) {
                int grow = rowBase + row;
                src = (grow < NN) ? (const void*)&g_x2b[(size_t)grow * F1 + k0 + c * 8]
                                  : (const void*)g_x2b;
                if (grow >= NN) bytes = 0;
            } else {
                src = &g_w2t[(size_t)(row - 128) * F1 + k0 + c * 8];
            }
            cp16(b0 + (row * SSTR + c * 4) * 4, src, bytes);
        }
    };

    float acc[2][4][4];
    #pragma unroll
    for (int mt = 0; mt < 2; mt++)
        #pragma unroll
        for (int nt = 0; nt < 4; nt++)
            #pragma unroll
            for (int i = 0; i < 4; i++) acc[mt][nt][i] = 0.f;

    stage_load(0, 0);
    cp_commit();

    #pragma unroll 1
    for (int it = 0; it < F1 / G1_BK; it++) {     // 4 iterations
        int buf = it & 1;
        if (it + 1 < F1 / G1_BK) {
            stage_load(buf ^ 1, (it + 1) * G1_BK);
            cp_commit();
            cp_wait<1>();
        } else {
            cp_wait<0>();
        }
        __syncthreads();

        const uint32_t* Sb = &S[buf][0];
        #pragma unroll
        for (int ks = 0; ks < 2; ks++) {
            uint32_t a[2][4];
            #pragma unroll
            for (int mt = 0; mt < 2; mt++) {
                int r0 = (wm * 32 + mt * 16 + g) * SSTR + ks * 8 + t4;
                a[mt][0] = Sb[r0];
                a[mt][1] = Sb[r0 + 8 * SSTR];
                a[mt][2] = Sb[r0 + 4];
                a[mt][3] = Sb[r0 + 8 * SSTR + 4];
            }
            #pragma unroll
            for (int nt = 0; nt < 4; nt++) {
                int bi = (128 + wn * 32 + nt * 8 + g) * SSTR + ks * 8 + t4;
                uint32_t b[2] = {Sb[bi], Sb[bi + 4]};
                mma_bf16(acc[0][nt], a[0], b);
                mma_bf16(acc[1][nt], a[1], b);
            }
        }
        __syncthreads();
    }

    // epilogue: write h2 f32 (cols < 40 only)
    #pragma unroll
    for (int mt = 0; mt < 2; mt++) {
        int row = rowBase + wm * 32 + mt * 16 + g;
        #pragma unroll
        for (int nt = 0; nt < 4; nt++) {
            int col = wn * 32 + nt * 8 + 2 * t4;
            if (col < F2) {
                if (row < NN)
                    *(float2*)&g_h2[(size_t)row * F2 + col] =
                        make_float2(acc[mt][nt][0], acc[mt][nt][1]);
                if (row + 8 < NN)
                    *(float2*)&g_h2[(size_t)(row + 8) * F2 + col] =
                        make_float2(acc[mt][nt][2], acc[mt][nt][3]);
            }
        }
    }
}

// ---------------- layer-2 attention coefficients -----------------------------
__global__ __launch_bounds__(256) void k_attc2(const float* __restrict__ att_src2,
                                               const float* __restrict__ att_dst2) {
    int warpId = (blockIdx.x * blockDim.x + threadIdx.x) >> 5;
    int lane = threadIdx.x & 31;
    if (warpId >= NN) return;
    const float* hr = &g_h2[(size_t)warpId * F2];
    float v0 = hr[lane];
    float v1 = (lane < 8) ? hr[32 + lane] : 0.f;
    float ps = v0 * att_src2[lane] + ((lane < 8) ? v1 * att_src2[32 + lane] : 0.f);
    float pd = v0 * att_dst2[lane] + ((lane < 8) ? v1 * att_dst2[32 + lane] : 0.f);
    #pragma unroll
    for (int off = 16; off > 0; off >>= 1) {
        ps += __shfl_xor_sync(0xffffffffu, ps, off);
        pd += __shfl_xor_sync(0xffffffffu, pd, off);
    }
    if (lane == 0) { g_asrc2[warpId] = ps; g_adst2[warpId] = pd; }
}

// ---------------- edge exp, layer 2 ------------------------------------------
__global__ void k_edgee2() {
    int j = blockIdx.x * blockDim.x + threadIdx.x;
    if (j >= TOT) return;
    int s = g_esrc[j], d = g_edst[j];
    g_alpha2[j] = __expf(leaky(g_asrc2[s] + g_adst2[d]));
}

// ---------------- layer-2 aggregate + log_softmax ----------------------------
__global__ __launch_bounds__(256) void k_agg2(const float* __restrict__ b2,
                                              float* __restrict__ out) {
    int warpId = (blockIdx.x * blockDim.x + threadIdx.x) >> 5;
    int lane = threadIdx.x & 31;
    if (warpId >= NN) return;
    int n = warpId;
    int start = g_rowptr[n], end = g_rowptr[n + 1];

    float dsum = 0.f;
    for (int j = start + lane; j < end; j += 32)
        dsum += g_alpha2[j];
    #pragma unroll
    for (int off = 16; off > 0; off >>= 1)
        dsum += __shfl_xor_sync(0xffffffffu, dsum, off);
    float inv = 1.f / (dsum + 1e-16f);

    float acc0 = 0.f, acc1 = 0.f;
    for (int j = start; j < end; j++) {
        int s = g_esrc[j];
        float aq = g_alpha2[j];
        const float* hr = &g_h2[(size_t)s * F2];
        acc0 = fmaf(hr[lane], aq, acc0);
        if (lane < 8) acc1 = fmaf(hr[32 + lane], aq, acc1);
    }
    float v0 = acc0 * inv + b2[lane];
    float v1 = (lane < 8) ? (acc1 * inv + b2[32 + lane]) : -INFINITY;

    float mx = fmaxf(v0, v1);
    #pragma unroll
    for (int off = 16; off > 0; off >>= 1)
        mx = fmaxf(mx, __shfl_xor_sync(0xffffffffu, mx, off));
    float se = __expf(v0 - mx) + ((lane < 8) ? __expf(v1 - mx) : 0.f);
    #pragma unroll
    for (int off = 16; off > 0; off >>= 1)
        se += __shfl_xor_sync(0xffffffffu, se, off);
    float lse = mx + logf(se);

    float* o = &out[(size_t)n * F2];
    o[lane] = v0 - lse;
    if (lane < 8) o[32 + lane] = v1 - lse;
}

// ---------------- launch ------------------------------------------------------
extern "C" void kernel_launch(void* const* d_in, const int* in_sizes, int n_in,
                              void* d_out, int out_size) {
    const float* x   = (const float*)d_in[0];
    const int*   ei  = (const int*)d_in[1];
    const float* W1  = (const float*)d_in[2];
    const float* as1 = (const float*)d_in[3];
    const float* ad1 = (const float*)d_in[4];
    const float* b1  = (const float*)d_in[5];
    const float* W2  = (const float*)d_in[6];
    const float* as2 = (const float*)d_in[7];
    const float* ad2 = (const float*)d_in[8];
    const float* b2  = (const float*)d_in[9];
    float* out = (float*)d_out;

    k_convw<<<(F1 * FIN + 255) / 256, 256>>>(W1, W2, ei);
    k_hist<<<(EE + 255) / 256, 256>>>(ei);
    k_scan<<<1, SCAN_T>>>();
    k_gemm1<<<(NN + G1_BM - 1) / G1_BM, 256>>>(x);   // 4th launch → profiled
    k_scatter<<<(TOT + 255) / 256, 256>>>(ei);

    k_attc1<<<(NN * H1 + 255) / 256, 256>>>(as1, ad1);
    k_edgee1<<<(TOT * H1 + 255) / 256, 256>>>();
    k_agg1<<<(NN + 7) / 8, 256>>>(b1);

    k_gemm2<<<(NN + 127) / 128, 256>>>();
    k_attc2<<<(NN + 7) / 8, 256>>>(as2, ad2);
    k_edgee2<<<(TOT + 255) / 256, 256>>>();
    k_agg2<<<(NN + 7) / 8, 256>>>(b2, out);
}